// round 13
// baseline (speedup 1.0000x reference)
#include <cuda_runtime.h>
#include <cuda_bf16.h>
#include <cstdint>

// ---------------------------------------------------------------------------
// Problem constants
// ---------------------------------------------------------------------------
#define D_IN   992
#define HID    32
#define NKS    62            // 992 / 16 k-steps
#define KPH    31            // k-steps per phase (2 phases)
#define TMROWS 128           // rows per CTA (8 warps x 1 m-tile)

// W in mma B-fragment layout (k-permuted), bf16 hi/lo packed per lane:
// [ks 62][nt 4][lane 32] -> uint4 (bh0, bh1, bl0, bl1)
__device__ uint4 g_Wf[NKS * 4 * 32];

// ---------------------------------------------------------------------------
// dynamic smem layout (floats).  W phase buffer occupies [0, 15872); after the
// mainloop it is dead, so hs/pp overlay it.  KAN tables live beyond it.
// ---------------------------------------------------------------------------
#define SM_W    0                          // 31*4*32 uint4 = 15872 floats (63.5KB)
#define SM_HS   0                          // 128*33 = 4224   (overlays dead W)
#define SM_PP   4224                       // 128*33 = 4224   (overlays dead W)
#define SM_CW0  15872                      // 32*20*6 = 3840 (j padded -4..15)
#define SM_WB0  19712                      // 32*6 = 192
#define SM_CW1  19904                      // 6*20 = 120 (j padded)
#define SM_WB1  20024                      // 6
#define SM_B0   20030                      // 6
#define SM_B1   20036                      // 1
#define SM_TOTF 20040
#define SM_BYTES (SM_TOTF * 4)             // 80160 -> 2 CTAs/SM

// ---------------------------------------------------------------------------
// helpers
// ---------------------------------------------------------------------------
__device__ __forceinline__ uint32_t packbf(float e0, float e1) {
    uint32_t r;
    asm("cvt.rn.bf16x2.f32 %0, %1, %2;" : "=r"(r) : "f"(e1), "f"(e0));
    return r;
}
__device__ __forceinline__ void unpackbf(uint32_t p, float& e0, float& e1) {
    e0 = __uint_as_float(p << 16);
    e1 = __uint_as_float(p & 0xFFFF0000u);
}
__device__ __forceinline__ void mma_bf16(float d[4], uint32_t a0, uint32_t a1,
                                         uint32_t a2, uint32_t a3,
                                         uint32_t b0, uint32_t b1) {
    asm volatile(
        "mma.sync.aligned.m16n8k16.row.col.f32.bf16.bf16.f32 "
        "{%0,%1,%2,%3}, {%4,%5,%6,%7}, {%8,%9}, {%0,%1,%2,%3};"
        : "+f"(d[0]), "+f"(d[1]), "+f"(d[2]), "+f"(d[3])
        : "r"(a0), "r"(a1), "r"(a2), "r"(a3), "r"(b0), "r"(b1));
}

// f32x2 packed helpers (KAN phase)
__device__ __forceinline__ uint64_t f2dup(float x) {
    uint64_t r; asm("mov.b64 %0, {%1, %1};" : "=l"(r) : "f"(x)); return r;
}
__device__ __forceinline__ void f2unpack(uint64_t v, float& x, float& y) {
    asm("mov.b64 {%0, %1}, %2;" : "=f"(x), "=f"(y) : "l"(v));
}
__device__ __forceinline__ void ffma2(uint64_t& d, uint64_t a, uint64_t b) {
    asm("fma.rn.f32x2 %0, %1, %2, %0;" : "+l"(d) : "l"(a), "l"(b));
}

// degree-4 uniform B-spline basis (5 nonzero values), matches reference
__device__ __forceinline__ void bspline4(float u, float bw[5]) {
    const float um = 1.f - u;
    float c0 = um, c1 = u;
    float d0 = 0.5f * (um * c0);
    float d1 = 0.5f * ((u + 1.f) * c0 + (2.f - u) * c1);
    float d2 = 0.5f * (u * c1);
    const float i3 = 1.f / 3.f;
    float e0 = i3 * (um * d0);
    float e1 = i3 * ((u + 2.f) * d0 + (2.f - u) * d1);
    float e2 = i3 * ((u + 1.f) * d1 + (3.f - u) * d2);
    float e3 = i3 * (u * d2);
    bw[0] = 0.25f * (um * e0);
    bw[1] = 0.25f * ((u + 3.f) * e0 + (2.f - u) * e1);
    bw[2] = 0.25f * ((u + 2.f) * e1 + (3.f - u) * e2);
    bw[3] = 0.25f * ((u + 1.f) * e2 + (4.f - u) * e3);
    bw[4] = 0.25f * (u * e3);
}
__device__ __forceinline__ float silu_f(float x) { return x / (1.f + __expf(-x)); }

// ---------------------------------------------------------------------------
// W pre-conversion with k-permutation:
// lane (g,t4), nt: b0 = {W[ks16+4t4][n], W[ks16+4t4+1][n]},
//                  b1 = {W[ks16+4t4+2][n], W[ks16+4t4+3][n]}, n = nt*8+g
// ---------------------------------------------------------------------------
__global__ void wfrag_kernel(const float* __restrict__ W) {
    int idx = blockIdx.x * 256 + threadIdx.x;     // 62*4*32 = 7936
    if (idx >= NKS * 4 * 32) return;
    int lane = idx & 31;
    int nt   = (idx >> 5) & 3;
    int ks   = idx >> 7;
    int g = lane >> 2, t4 = lane & 3;
    int n  = nt * 8 + g;
    int ka = ks * 16 + t4 * 4;

    float x0 = W[(ka + 0) * HID + n];
    float x1 = W[(ka + 1) * HID + n];
    float y0 = W[(ka + 2) * HID + n];
    float y1 = W[(ka + 3) * HID + n];

    uint32_t h0 = packbf(x0, x1), h1 = packbf(y0, y1);
    float e0, e1;
    unpackbf(h0, e0, e1);
    uint32_t l0 = packbf(x0 - e0, x1 - e1);
    unpackbf(h1, e0, e1);
    uint32_t l1 = packbf(y0 - e0, y1 - e1);

    g_Wf[idx] = make_uint4(h0, h1, l0, l1);
}

// ---------------------------------------------------------------------------
// One GEMM k-step (BUF literal). W from smem (LDS.128, conflict-free),
// A consumed from av[BUF] and refilled with global step KPRE (clamped).
// 12 mma, single m-tile.
// ---------------------------------------------------------------------------
#define GEMM_STEP(BUF, WIDX, KPRE)                                             \
{                                                                              \
    uint4 w[4];                                                                \
    _Pragma("unroll")                                                          \
    for (int nt = 0; nt < 4; nt++)                                             \
        w[nt] = ws[((WIDX) * 4 + nt) * 32 + lane];                             \
    float4 a0 = av[BUF][0];                                                    \
    float4 a1 = av[BUF][1];                                                    \
    {                                                                          \
        const int _kp = (KPRE);                                                \
        av[BUF][0] = __ldcs((const float4*)(pA0 + _kp * 16));                  \
        av[BUF][1] = __ldcs((const float4*)(pA1 + _kp * 16));                  \
    }                                                                          \
    uint32_t ah0 = packbf(a0.x, a0.y);                                         \
    uint32_t ah1 = packbf(a1.x, a1.y);                                         \
    uint32_t ah2 = packbf(a0.z, a0.w);                                         \
    uint32_t ah3 = packbf(a1.z, a1.w);                                         \
    float e0, e1;                                                              \
    uint32_t al0, al1, al2, al3;                                               \
    unpackbf(ah0, e0, e1); al0 = packbf(a0.x - e0, a0.y - e1);                 \
    unpackbf(ah1, e0, e1); al1 = packbf(a1.x - e0, a1.y - e1);                 \
    unpackbf(ah2, e0, e1); al2 = packbf(a0.z - e0, a0.w - e1);                 \
    unpackbf(ah3, e0, e1); al3 = packbf(a1.z - e0, a1.w - e1);                 \
    _Pragma("unroll")                                                          \
    for (int nt = 0; nt < 4; nt++) {                                           \
        mma_bf16(acc[nt], ah0, ah1, ah2, ah3, w[nt].x, w[nt].y);               \
        mma_bf16(acc[nt], ah0, ah1, ah2, ah3, w[nt].z, w[nt].w);               \
        mma_bf16(acc[nt], al0, al1, al2, al3, w[nt].x, w[nt].y);               \
    }                                                                          \
}

// ---------------------------------------------------------------------------
// Fused kernel: smem-resident W (2 k-phases), 8 warps x 1 m-tile,
// accumulators persist across phases (no partial combine).
// ---------------------------------------------------------------------------
__global__ void __launch_bounds__(256, 2)
fused_kernel(const float* __restrict__ A, const float* __restrict__ bias,
             const float* __restrict__ coef0, const float* __restrict__ wb0,
             const float* __restrict__ ws0,   const float* __restrict__ b0,
             const float* __restrict__ coef1, const float* __restrict__ wb1,
             const float* __restrict__ ws1,   const float* __restrict__ b1,
             float* __restrict__ out, int N)
{
    extern __shared__ __align__(16) float smem[];
    uint4* wsm  = (uint4*)(smem + SM_W);   // W phase buffer (3968 uint4)
    const uint4* ws = wsm;
    float* hs   = smem + SM_HS;            // hidden (overlays dead W)
    float* pp   = smem + SM_PP;            // KAN partials (overlays dead W)
    float* cw0p = smem + SM_CW0;
    float* wb0s = smem + SM_WB0;
    float* cw1p = smem + SM_CW1;
    float* wb1s = smem + SM_WB1;
    float* b0s  = smem + SM_B0;
    float* b1s  = smem + SM_B1;

    const int tid  = threadIdx.x;
    const int warp = tid >> 5;             // m-tile id (rows warp*16..+15)
    const int lane = tid & 31;
    const int g    = lane >> 2;
    const int t4   = lane & 3;
    const int row0 = blockIdx.x * TMROWS;

    // ---- stage KAN tables (outside W region; no barrier needed yet) ----
    for (int idx = tid; idx < 32 * 20 * 6; idx += 256) {
        int i = idx / 120, rem = idx % 120, jj = rem / 6, o = rem % 6;
        int j = jj - 4;
        cw0p[idx] = (j >= 0 && j < 12)
                  ? coef0[(i * 6 + o) * 12 + j] * ws0[i * 6 + o] : 0.f;
    }
    if (tid < 32 * 6) wb0s[tid] = wb0[tid];
    if (tid < 120) {
        int i = tid / 20, jj = tid % 20, j = jj - 4;
        cw1p[tid] = (j >= 0 && j < 12) ? coef1[i * 12 + j] * ws1[i] : 0.f;
    }
    if (tid < 6)  { wb1s[tid] = wb1[tid]; b0s[tid] = b0[tid]; }
    if (tid == 0) b1s[0] = b1[0];

    // ---- stage W phase 0 into smem ----
    {
        const uint4* src = g_Wf;                       // ks 0..30
        for (int i = tid; i < KPH * 4 * 32; i += 256) wsm[i] = src[i];
    }

    // ---- A row pointers (single m-tile) ----
    int r0 = row0 + warp * 16 + g;
    int r1 = r0 + 8;
    if (r0 > N - 1) r0 = N - 1;
    if (r1 > N - 1) r1 = N - 1;
    const float* pA0 = A + (size_t)r0 * D_IN + t4 * 4;
    const float* pA1 = A + (size_t)r1 * D_IN + t4 * 4;

    // ---- depth-2 A prefetch (global steps 0,1) ----
    float4 av[2][2];
    av[0][0] = __ldcs((const float4*)(pA0));
    av[0][1] = __ldcs((const float4*)(pA1));
    av[1][0] = __ldcs((const float4*)(pA0 + 16));
    av[1][1] = __ldcs((const float4*)(pA1 + 16));

    float acc[4][4];
    #pragma unroll
    for (int nt = 0; nt < 4; nt++)
        #pragma unroll
        for (int r = 0; r < 4; r++) acc[nt][r] = 0.f;

    __syncthreads();   // W phase 0 visible

    // ---- phase 0: global k-steps 0..30 (buf parity = global step parity) ----
    for (int s = 0; s + 1 < KPH; s += 2) {
        GEMM_STEP(0, s,     s + 2);
        GEMM_STEP(1, s + 1, s + 3);
    }
    GEMM_STEP(0, KPH - 1, KPH + 1);        // step 30, prefetch 32 (31 already in buf1)

    // ---- stage W phase 1 ----
    __syncthreads();                        // all warps done reading phase 0
    {
        const uint4* src = g_Wf + KPH * 4 * 32;        // ks 31..61
        for (int i = tid; i < KPH * 4 * 32; i += 256) wsm[i] = src[i];
    }
    __syncthreads();                        // W phase 1 visible

    // ---- phase 1: global k-steps 31..61 (31 odd -> buf1 first) ----
    for (int s = 0; s + 1 < KPH; s += 2) {
        const int p0 = (33 + s < NKS) ? 33 + s : NKS - 1;
        const int p1 = (34 + s < NKS) ? 34 + s : NKS - 1;
        GEMM_STEP(1, s,     p0);
        GEMM_STEP(0, s + 1, p1);
    }
    GEMM_STEP(1, KPH - 1, NKS - 1);        // global step 61 (prefetch redundant)

    // ---- epilogue: bias add + transpose (W buffer dead; hs overlays it) ----
    __syncthreads();                        // last W reads complete before overwrite
    #pragma unroll
    for (int nt = 0; nt < 4; nt++) {
        float2 bv = *(const float2*)&bias[nt * 8 + t4 * 2];
        int rl = warp * 16 + g;
        int c0 = nt * 8 + t4 * 2;
        hs[rl * 33 + c0]           = acc[nt][0] + bv.x;
        hs[rl * 33 + c0 + 1]       = acc[nt][1] + bv.y;
        hs[(rl + 8) * 33 + c0]     = acc[nt][2] + bv.x;
        hs[(rl + 8) * 33 + c0 + 1] = acc[nt][3] + bv.y;
    }
    __syncthreads();

    // ---- KAN layer 0: 2 threads per row, each handles 16 of 32 inputs ----
    const int r = tid & 127;          // row within CTA
    const int h = tid >> 7;           // half (0: i 0..15, 1: i 16..31)

    uint64_t kacc[3];
    kacc[0] = kacc[1] = kacc[2] = 0ull;

    #pragma unroll
    for (int i2 = 0; i2 < 16; i2++) {
        const int i = h * 16 + i2;
        float x  = hs[r * 33 + i];
        float sg = silu_f(x);
        uint64_t sgd = f2dup(sg);
        const uint64_t* wbp = (const uint64_t*)&wb0s[i * 6];
        ffma2(kacc[0], sgd, wbp[0]);
        ffma2(kacc[1], sgd, wbp[1]);
        ffma2(kacc[2], sgd, wbp[2]);

        float t = (x + 2.f) * 4.f;
        if (t >= 0.f && t < 16.f) {
            float cf = floorf(t);
            int   c  = (int)cf;
            float u  = t - cf;
            float bw[5];
            bspline4(u, bw);
            const float* base = &cw0p[i * 120 + c * 6];   // tap k -> base + k*6
            #pragma unroll
            for (int k = 0; k < 5; k++) {
                uint64_t bd = f2dup(bw[k]);
                const uint64_t* cp = (const uint64_t*)(base + k * 6);
                ffma2(kacc[0], bd, cp[0]);
                ffma2(kacc[1], bd, cp[1]);
                ffma2(kacc[2], bd, cp[2]);
            }
        }
    }
    __syncthreads();                     // pp region free
    {
        float p0, p1, p2, p3, p4, p5;
        f2unpack(kacc[0], p0, p1);
        f2unpack(kacc[1], p2, p3);
        f2unpack(kacc[2], p4, p5);
        float* q = &pp[r * 12 + h * 6];
        q[0] = p0; q[1] = p1; q[2] = p2;
        q[3] = p3; q[4] = p4; q[5] = p5;
    }
    __syncthreads();

    // ---- KAN layer 1 (half 0 threads only) ----
    if (h == 0) {
        const int row = row0 + r;
        if (row < N) {
            float res = b1s[0];
            #pragma unroll
            for (int i = 0; i < 6; i++) {
                float x = pp[r * 12 + i] + pp[r * 12 + 6 + i] + b0s[i];
                res += silu_f(x) * wb1s[i];
                float t = (x + 2.f) * 4.f;
                if (t >= 0.f && t < 16.f) {
                    float cf = floorf(t);
                    int   c  = (int)cf;
                    float u  = t - cf;
                    float bw[5];
                    bspline4(u, bw);
                    const float* base = &cw1p[i * 20 + c];
                    #pragma unroll
                    for (int k = 0; k < 5; k++)
                        res += bw[k] * base[k];
                }
            }
            out[row] = res;
        }
    }
}

// ---------------------------------------------------------------------------
// Launch
// ---------------------------------------------------------------------------
extern "C" void kernel_launch(void* const* d_in, const int* in_sizes, int n_in,
                              void* d_out, int out_size)
{
    const float* node_rep = (const float*)d_in[0];
    const float* mlp_w    = (const float*)d_in[1];
    const float* mlp_b    = (const float*)d_in[2];
    const float* coef0    = (const float*)d_in[3];
    const float* wb0      = (const float*)d_in[4];
    const float* ws0      = (const float*)d_in[5];
    const float* b0       = (const float*)d_in[6];
    const float* coef1    = (const float*)d_in[7];
    const float* wb1      = (const float*)d_in[8];
    const float* ws1      = (const float*)d_in[9];
    const float* b1       = (const float*)d_in[10];

    int N = in_sizes[0] / D_IN;

    cudaFuncSetAttribute(fused_kernel,
                         cudaFuncAttributeMaxDynamicSharedMemorySize, SM_BYTES);

    wfrag_kernel<<<(NKS * 4 * 32 + 255) / 256, 256>>>(mlp_w);
    fused_kernel<<<(N + TMROWS - 1) / TMROWS, 256, SM_BYTES>>>(
        node_rep, mlp_b, coef0, wb0, ws0, b0, coef1, wb1, ws1, b1,
        (float*)d_out, N);
}